// round 11
// baseline (speedup 1.0000x reference)
#include <cuda_runtime.h>

// ---------------------------------------------------------------------------
// CustomSTFT collapses algebraically to  out[b,n] = x[b,n] * W[n],
// where W is (400/401) * overlap-added hann weights: periodic with period 200
// except the first/last 200 samples -> 600-float table, computed at COMPILE
// TIME (constexpr Taylor sin). Single graph node.
//
// R10: __stcs evict-first stores stopped the output stream evicting the input
// from L2 (22.6 -> 16.9us). Profile is now latency/issue-bound (nothing >53%).
// R11: collapse the 8 per-thread mod chains to 2 (base%50, base%120000 once;
// per-v values via add + conditional subtract since stride 256 === 6 mod 50).
// ---------------------------------------------------------------------------

#define HOP    200
#define TLEN   480000
#define NBATCH 32
#define ROW4   (TLEN / 4)            // 120000 float4 per row
#define TOTAL4 (NBATCH * ROW4)       // 3,840,000
#define VPT    4                     // float4s per thread
#define TPB    256
#define NBLK   (TOTAL4 / (TPB * VPT))  // 3750 exactly

// ---- compile-time table ----------------------------------------------------
constexpr double C_PI = 3.14159265358979323846;

// Taylor sin, |x| <= pi/2, terms through x^19 (abs err < 1e-16).
constexpr double tsin(double x) {
    double x2 = x * x, t = x, s = x;
    t *= -x2 / (2.0 * 3.0);   s += t;
    t *= -x2 / (4.0 * 5.0);   s += t;
    t *= -x2 / (6.0 * 7.0);   s += t;
    t *= -x2 / (8.0 * 9.0);   s += t;
    t *= -x2 / (10.0 * 11.0); s += t;
    t *= -x2 / (12.0 * 13.0); s += t;
    t *= -x2 / (14.0 * 15.0); s += t;
    t *= -x2 / (16.0 * 17.0); s += t;
    t *= -x2 / (18.0 * 19.0); s += t;
    return s;
}

// np.hanning(800)[w] = 0.5 - 0.5*cos(2*pi*w/799) = sin^2(pi*w/799)
constexpr double hann(int w) {
    double a = C_PI * (double)w / 799.0;           // in [0, pi]
    double r = (a > C_PI * 0.5) ? (C_PI - a) : a;  // sin(pi-a) = sin(a)
    double s = tsin(r);
    return s * s;
}

struct alignas(16) Tab {
    float v[600];
    constexpr Tab() : v() {
        for (int t = 0; t < 600; t++) {
            int seg = t / HOP, r = t % HOP;
            double s = 0.0;
            if (seg < 2) s += hann(r);           // head+interior include frame j=0
            s += hann(r + 200) + hann(r + 400);
            if (seg > 0) s += hann(r + 600);     // interior+tail include frame j=3
            v[t] = (float)(s * (400.0 / 401.0));
        }
    }
};

__device__ const Tab c_tab = Tab();   // constexpr static init — no setup kernel

// ---- main kernel -----------------------------------------------------------
// Flat 1D, 4 front-batched float4 loads per thread, block-stride (each LDG
// wave is 512B contiguous per warp). No bounds checks: grid divides exactly.
// Index math: two mods per THREAD (not per element); per-v values derived by
// add + conditional subtract (stride TPB=256: 256 mod 50 = 6).
// Stores: __stcs evict-first (don't displace the input in L2 across replays).
__global__ void __launch_bounds__(TPB) k_scale(const float4* __restrict__ in,
                                               float4* __restrict__ out) {
    const float4* tab4 = (const float4*)c_tab.v;   // 2.4KB, L1-resident
    unsigned base = blockIdx.x * (TPB * VPT) + threadIdx.x;

    float4 x[VPT];
#pragma unroll
    for (int v = 0; v < VPT; v++)
        x[v] = in[base + v * TPB];                 // 4 independent loads up front

    unsigned r0 = base % 50u;                      // pos within 200-sample period
    unsigned m0 = base % (unsigned)ROW4;           // pos within batch row

#pragma unroll
    for (int v = 0; v < VPT; v++) {
        unsigned r = r0 + 6u * v;   if (r >= 50u) r -= 50u;
        unsigned m = m0 + 256u * v; if (m >= (unsigned)ROW4) m -= (unsigned)ROW4;
        unsigned seg = (m < 50u) ? 0u : ((m >= (unsigned)(ROW4 - 50)) ? 100u : 50u);
        float4 w = __ldg(tab4 + seg + r);
        x[v].x *= w.x; x[v].y *= w.y; x[v].z *= w.z; x[v].w *= w.w;
        __stcs(out + base + v * TPB, x[v]);        // streaming store, evict-first
    }
}

extern "C" void kernel_launch(void* const* d_in, const int* in_sizes, int n_in,
                              void* d_out, int out_size) {
    const float4* in  = (const float4*)d_in[0];
    float4*       out = (float4*)d_out;

    k_scale<<<NBLK, TPB>>>(in, out);               // single graph node, 3750 blocks
}